// round 4
// baseline (speedup 1.0000x reference)
#include <cuda_runtime.h>

#define MAXN 100000

// Static scratch (no allocation allowed)
__device__ float  d_agg1[MAXN * 8];   // x (padded) + sum x[src], per dst
__device__ float  d_g[MAXN * 32];     // g = h_A @ w1b
__device__ float  d_agg2[MAXN * 32];  // sum g[src], per dst
__device__ float2 d_sc[MAXN];         // (s0, s1) per node

// kA: agg1 <- [x, 0], agg2 <- 0
__global__ void kA_init(const float* __restrict__ x, int N) {
    int n = blockIdx.x * blockDim.x + threadIdx.x;
    if (n >= N) return;
    const float* xr = x + (size_t)n * 7;
    float4* a1 = (float4*)(d_agg1 + n * 8);
    a1[0] = make_float4(__ldg(xr), __ldg(xr + 1), __ldg(xr + 2), __ldg(xr + 3));
    a1[1] = make_float4(__ldg(xr + 4), __ldg(xr + 5), __ldg(xr + 6), 0.f);
    float4 z = make_float4(0.f, 0.f, 0.f, 0.f);
    float4* a2 = (float4*)(d_agg2 + n * 32);
#pragma unroll
    for (int q = 0; q < 8; q++) a2[q] = z;
}

// k1: agg1[dst][j] += x[src][j].  8 lanes per edge, 4 edges per warp.
__global__ void __launch_bounds__(256) k1_scat1(const int* __restrict__ ei,
                                                const float* __restrict__ x, int E) {
    int t = blockIdx.x * blockDim.x + threadIdx.x;
    int e = (t >> 5) * 4 + ((t & 31) >> 3);   // edge id
    int j = t & 7;                            // feature lane
    if (e >= E || j >= 7) return;
    int s = __ldg(ei + e);
    int d = __ldg(ei + E + e);
    float v = __ldg(x + (size_t)s * 7 + j);
    atomicAdd(d_agg1 + d * 8 + j, v);         // return unused -> REDG
}

// k2: per node: t[7] -> relu(t@w1a+b1a) -> @w2a+b2a -> relu -> @w1b = g[32]
__global__ void __launch_bounds__(128) k2_mlpA(
    const float* __restrict__ w1a, const float* __restrict__ b1a,
    const float* __restrict__ w2a, const float* __restrict__ b2a,
    const float* __restrict__ w1b, int N) {
    __shared__ float s_w1a[7 * 64];
    __shared__ float s_b1a[64];
    __shared__ float s_w2a[64 * 64];
    __shared__ float s_b2a[64];
    __shared__ float s_w1b[64 * 32];
    for (int i = threadIdx.x; i < 7 * 64; i += 128) s_w1a[i] = w1a[i];
    if (threadIdx.x < 64) { s_b1a[threadIdx.x] = b1a[threadIdx.x]; s_b2a[threadIdx.x] = b2a[threadIdx.x]; }
    for (int i = threadIdx.x; i < 64 * 64; i += 128) s_w2a[i] = w2a[i];
    for (int i = threadIdx.x; i < 64 * 32; i += 128) s_w1b[i] = w1b[i];
    __syncthreads();

    int n = blockIdx.x * 128 + threadIdx.x;
    if (n >= N) return;

    float tin[7];
    const float* tr = d_agg1 + n * 8;
#pragma unroll
    for (int i = 0; i < 7; i++) tin[i] = tr[i];

    float acc[64];
#pragma unroll
    for (int j = 0; j < 64; j++) acc[j] = 0.f;
#pragma unroll 1
    for (int k = 0; k < 64; k++) {
        float h = s_b1a[k];
#pragma unroll
        for (int i = 0; i < 7; i++) h = fmaf(tin[i], s_w1a[i * 64 + k], h);
        h = fmaxf(h, 0.f);
#pragma unroll
        for (int j = 0; j < 64; j++) acc[j] = fmaf(h, s_w2a[k * 64 + j], acc[j]);
    }

    float g[32];
#pragma unroll
    for (int j = 0; j < 32; j++) g[j] = 0.f;
#pragma unroll 1
    for (int k = 0; k < 64; k++) {
        float h = fmaxf(acc[k] + s_b2a[k], 0.f);   // outer relu of layer A
#pragma unroll
        for (int j = 0; j < 32; j++) g[j] = fmaf(h, s_w1b[k * 32 + j], g[j]);
    }

    float4* gout = (float4*)(d_g + n * 32);
#pragma unroll
    for (int q = 0; q < 8; q++)
        gout[q] = make_float4(g[4 * q], g[4 * q + 1], g[4 * q + 2], g[4 * q + 3]);
}

// k3: agg2[dst][lane] += g[src][lane].  Warp per edge — fully coalesced gather + RED.
__global__ void __launch_bounds__(256) k3_scat2(const int* __restrict__ ei, int E) {
    int t = blockIdx.x * blockDim.x + threadIdx.x;
    int e = t >> 5;
    int lane = t & 31;
    if (e >= E) return;
    int s = __ldg(ei + e);        // broadcast within warp
    int d = __ldg(ei + E + e);
    float v = __ldg(d_g + (size_t)s * 32 + lane);   // 128B coalesced
    atomicAdd(d_agg2 + (size_t)d * 32 + lane, v);    // 128B coalesced RED
}

// k4: per node: a = relu(g + agg2 + b1b); h2 = a@w2b + b2b; s0 = h2.ws0, s1 = h2.ws1
__global__ void __launch_bounds__(128) k4_mlpB(
    const float* __restrict__ b1b, const float* __restrict__ w2b,
    const float* __restrict__ b2b, const float* __restrict__ ws, int N) {
    __shared__ float s_w2b[32 * 32];
    __shared__ float s_b1b[32];
    __shared__ float s_b2b[32];
    __shared__ float s_ws[64];
    for (int i = threadIdx.x; i < 32 * 32; i += 128) s_w2b[i] = w2b[i];
    if (threadIdx.x < 32) { s_b1b[threadIdx.x] = b1b[threadIdx.x]; s_b2b[threadIdx.x] = b2b[threadIdx.x]; }
    if (threadIdx.x < 64) s_ws[threadIdx.x] = ws[threadIdx.x];
    __syncthreads();

    int n = blockIdx.x * 128 + threadIdx.x;
    if (n >= N) return;

    const float* gr = d_g + n * 32;
    const float* ar = d_agg2 + n * 32;
    float acc[32];
#pragma unroll
    for (int j = 0; j < 32; j++) acc[j] = 0.f;
#pragma unroll 1
    for (int k = 0; k < 32; k++) {
        float a = fmaxf(gr[k] + ar[k] + s_b1b[k], 0.f);
#pragma unroll
        for (int j = 0; j < 32; j++) acc[j] = fmaf(a, s_w2b[k * 32 + j], acc[j]);
    }
    float s0 = 0.f, s1 = 0.f;
#pragma unroll
    for (int j = 0; j < 32; j++) {
        float h = acc[j] + s_b2b[j];
        s0 = fmaf(h, s_ws[j], s0);
        s1 = fmaf(h, s_ws[32 + j], s1);
    }
    d_sc[n] = make_float2(s0, s1);
}

// k5: out[i] = sigmoid(s0[c0] + s1[c1] + bs)
__global__ void k5_score(const int* __restrict__ cand, const float* __restrict__ bs,
                         float* __restrict__ out, int C) {
    int i = blockIdx.x * blockDim.x + threadIdx.x;
    if (i >= C) return;
    int2 ce = __ldg((const int2*)cand + i);
    float z = d_sc[ce.x].x + d_sc[ce.y].y + __ldg(bs);
    out[i] = 1.f / (1.f + __expf(-z));
}

extern "C" void kernel_launch(void* const* d_in, const int* in_sizes, int n_in,
                              void* d_out, int out_size) {
    const float* x    = (const float*)d_in[0];
    const int*   ei   = (const int*)d_in[1];
    const int*   cand = (const int*)d_in[2];
    const float* w1a = (const float*)d_in[3];
    const float* b1a = (const float*)d_in[4];
    const float* w2a = (const float*)d_in[5];
    const float* b2a = (const float*)d_in[6];
    const float* w1b = (const float*)d_in[7];
    const float* b1b = (const float*)d_in[8];
    const float* w2b = (const float*)d_in[9];
    const float* b2b = (const float*)d_in[10];
    const float* ws  = (const float*)d_in[11];
    const float* bs  = (const float*)d_in[12];

    int N = in_sizes[0] / 7;
    int E = in_sizes[1] / 2;
    int C = in_sizes[2] / 2;
    float* out = (float*)d_out;

    kA_init <<<(N + 255) / 256, 256>>>(x, N);
    // k1: 8 threads per edge
    {
        long long th = (long long)((E + 3) / 4) * 32;
        k1_scat1<<<(unsigned)((th + 255) / 256), 256>>>(ei, x, E);
    }
    k2_mlpA <<<(N + 127) / 128, 128>>>(w1a, b1a, w2a, b2a, w1b, N);
    // k3: 32 threads per edge
    {
        long long th = (long long)E * 32;
        k3_scat2<<<(unsigned)((th + 255) / 256), 256>>>(ei, E);
    }
    k4_mlpB <<<(N + 127) / 128, 128>>>(b1b, w2b, b2b, ws, N);
    k5_score<<<(C + 255) / 256, 256>>>(cand, bs, out, C);
}

// round 5
// speedup vs baseline: 2.2763x; 2.2763x over previous
#include <cuda_runtime.h>

#define MAXN 100000

// Static scratch (no allocation allowed)
__device__ float  d_x8[MAXN * 8];     // x padded to 8 (32B rows)
__device__ float  d_agg1[MAXN * 8];   // x + sum x[src], per dst
__device__ float  d_g[MAXN * 32];     // g = h_A @ w1b (128B rows)
__device__ float  d_agg2[MAXN * 32];  // sum g[src], per dst
__device__ float2 d_sc[MAXN];         // (s0, s1) per node

__device__ __forceinline__ void red_add_v4(float* p, float4 v) {
    asm volatile("red.global.add.v4.f32 [%0], {%1, %2, %3, %4};"
                 :: "l"(p), "f"(v.x), "f"(v.y), "f"(v.z), "f"(v.w) : "memory");
}

// kA: x8 <- [x,0], agg1 <- x8, agg2 <- 0
__global__ void kA_init(const float* __restrict__ x, int N) {
    int n = blockIdx.x * blockDim.x + threadIdx.x;
    if (n >= N) return;
    const float* xr = x + (size_t)n * 7;
    float4 lo = make_float4(__ldg(xr), __ldg(xr + 1), __ldg(xr + 2), __ldg(xr + 3));
    float4 hi = make_float4(__ldg(xr + 4), __ldg(xr + 5), __ldg(xr + 6), 0.f);
    ((float4*)(d_x8 + n * 8))[0] = lo;
    ((float4*)(d_x8 + n * 8))[1] = hi;
    ((float4*)(d_agg1 + n * 8))[0] = lo;
    ((float4*)(d_agg1 + n * 8))[1] = hi;
    float4 z = make_float4(0.f, 0.f, 0.f, 0.f);
    float4* a2 = (float4*)(d_agg2 + n * 32);
#pragma unroll
    for (int q = 0; q < 8; q++) a2[q] = z;
}

// k1: agg1[dst] += x8[src].  2 lanes x float4 per edge, 16 edges per warp.
__global__ void __launch_bounds__(256) k1_scat1(const int* __restrict__ ei, int E) {
    int t = blockIdx.x * blockDim.x + threadIdx.x;
    int lane = t & 31;
    int e = (t >> 5) * 16 + (lane >> 1);
    int q = lane & 1;
    if (e >= E) return;
    int s = __ldg(ei + e);
    int d = __ldg(ei + E + e);
    float4 v = __ldg((const float4*)(d_x8 + (size_t)s * 8) + q);
    red_add_v4(d_agg1 + (size_t)d * 8 + q * 4, v);
}

// k2: per node: t[7] -> relu(t@w1a+b1a) -> @w2a+b2a -> relu -> @w1b = g[32]
__global__ void __launch_bounds__(128) k2_mlpA(
    const float* __restrict__ w1a, const float* __restrict__ b1a,
    const float* __restrict__ w2a, const float* __restrict__ b2a,
    const float* __restrict__ w1b, int N) {
    __shared__ float s_w1a[7 * 64];
    __shared__ float s_b1a[64];
    __shared__ float s_w2a[64 * 64];
    __shared__ float s_b2a[64];
    __shared__ float s_w1b[64 * 32];
    for (int i = threadIdx.x; i < 7 * 64; i += 128) s_w1a[i] = w1a[i];
    if (threadIdx.x < 64) { s_b1a[threadIdx.x] = b1a[threadIdx.x]; s_b2a[threadIdx.x] = b2a[threadIdx.x]; }
    for (int i = threadIdx.x; i < 64 * 64; i += 128) s_w2a[i] = w2a[i];
    for (int i = threadIdx.x; i < 64 * 32; i += 128) s_w1b[i] = w1b[i];
    __syncthreads();

    int n = blockIdx.x * 128 + threadIdx.x;
    if (n >= N) return;

    float tin[7];
    const float* tr = d_agg1 + n * 8;
#pragma unroll
    for (int i = 0; i < 7; i++) tin[i] = tr[i];

    float acc[64];
#pragma unroll
    for (int j = 0; j < 64; j++) acc[j] = 0.f;
#pragma unroll 1
    for (int k = 0; k < 64; k++) {
        float h = s_b1a[k];
#pragma unroll
        for (int i = 0; i < 7; i++) h = fmaf(tin[i], s_w1a[i * 64 + k], h);
        h = fmaxf(h, 0.f);
#pragma unroll
        for (int j = 0; j < 64; j++) acc[j] = fmaf(h, s_w2a[k * 64 + j], acc[j]);
    }

    float g[32];
#pragma unroll
    for (int j = 0; j < 32; j++) g[j] = 0.f;
#pragma unroll 1
    for (int k = 0; k < 64; k++) {
        float h = fmaxf(acc[k] + s_b2a[k], 0.f);   // outer relu of layer A
#pragma unroll
        for (int j = 0; j < 32; j++) g[j] = fmaf(h, s_w1b[k * 32 + j], g[j]);
    }

    float4* gout = (float4*)(d_g + n * 32);
#pragma unroll
    for (int q = 0; q < 8; q++)
        gout[q] = make_float4(g[4 * q], g[4 * q + 1], g[4 * q + 2], g[4 * q + 3]);
}

// k3: agg2[dst] += g[src].  8 lanes x float4 per edge, 4 edges per warp.
// Per edge: one 128B coalesced gather wavefront + one 128B RED wavefront.
__global__ void __launch_bounds__(256) k3_scat2(const int* __restrict__ ei, int E) {
    int t = blockIdx.x * blockDim.x + threadIdx.x;
    int lane = t & 31;
    int e = (t >> 5) * 4 + (lane >> 3);
    int q = lane & 7;
    if (e >= E) return;
    int s = __ldg(ei + e);
    int d = __ldg(ei + E + e);
    float4 v = __ldg((const float4*)(d_g + (size_t)s * 32) + q);
    red_add_v4(d_agg2 + (size_t)d * 32 + q * 4, v);
}

// k4: per node: a = relu(g + agg2 + b1b); h2 = a@w2b + b2b; s0/s1 = h2.ws halves
__global__ void __launch_bounds__(128) k4_mlpB(
    const float* __restrict__ b1b, const float* __restrict__ w2b,
    const float* __restrict__ b2b, const float* __restrict__ ws, int N) {
    __shared__ float s_w2b[32 * 32];
    __shared__ float s_b1b[32];
    __shared__ float s_b2b[32];
    __shared__ float s_ws[64];
    for (int i = threadIdx.x; i < 32 * 32; i += 128) s_w2b[i] = w2b[i];
    if (threadIdx.x < 32) { s_b1b[threadIdx.x] = b1b[threadIdx.x]; s_b2b[threadIdx.x] = b2b[threadIdx.x]; }
    if (threadIdx.x < 64) s_ws[threadIdx.x] = ws[threadIdx.x];
    __syncthreads();

    int n = blockIdx.x * 128 + threadIdx.x;
    if (n >= N) return;

    const float* gr = d_g + n * 32;
    const float* ar = d_agg2 + n * 32;
    float acc[32];
#pragma unroll
    for (int j = 0; j < 32; j++) acc[j] = 0.f;
#pragma unroll 1
    for (int k = 0; k < 32; k++) {
        float a = fmaxf(gr[k] + ar[k] + s_b1b[k], 0.f);
#pragma unroll
        for (int j = 0; j < 32; j++) acc[j] = fmaf(a, s_w2b[k * 32 + j], acc[j]);
    }
    float s0 = 0.f, s1 = 0.f;
#pragma unroll
    for (int j = 0; j < 32; j++) {
        float h = acc[j] + s_b2b[j];
        s0 = fmaf(h, s_ws[j], s0);
        s1 = fmaf(h, s_ws[32 + j], s1);
    }
    d_sc[n] = make_float2(s0, s1);
}

// k5: out[i] = sigmoid(s0[c0] + s1[c1] + bs)
__global__ void k5_score(const int* __restrict__ cand, const float* __restrict__ bs,
                         float* __restrict__ out, int C) {
    int i = blockIdx.x * blockDim.x + threadIdx.x;
    if (i >= C) return;
    int2 ce = __ldg((const int2*)cand + i);
    float z = d_sc[ce.x].x + d_sc[ce.y].y + __ldg(bs);
    out[i] = 1.f / (1.f + __expf(-z));
}

extern "C" void kernel_launch(void* const* d_in, const int* in_sizes, int n_in,
                              void* d_out, int out_size) {
    const float* x    = (const float*)d_in[0];
    const int*   ei   = (const int*)d_in[1];
    const int*   cand = (const int*)d_in[2];
    const float* w1a = (const float*)d_in[3];
    const float* b1a = (const float*)d_in[4];
    const float* w2a = (const float*)d_in[5];
    const float* b2a = (const float*)d_in[6];
    const float* w1b = (const float*)d_in[7];
    const float* b1b = (const float*)d_in[8];
    const float* w2b = (const float*)d_in[9];
    const float* b2b = (const float*)d_in[10];
    const float* ws  = (const float*)d_in[11];
    const float* bs  = (const float*)d_in[12];

    int N = in_sizes[0] / 7;
    int E = in_sizes[1] / 2;
    int C = in_sizes[2] / 2;
    float* out = (float*)d_out;

    kA_init <<<(N + 255) / 256, 256>>>(x, N);
    {   // k1: 2 threads per edge (16 edges/warp)
        long long warps = (E + 15) / 16;
        k1_scat1<<<(unsigned)((warps * 32 + 255) / 256), 256>>>(ei, E);
    }
    k2_mlpA <<<(N + 127) / 128, 128>>>(w1a, b1a, w2a, b2a, w1b, N);
    {   // k3: 8 threads per edge (4 edges/warp)
        long long warps = (E + 3) / 4;
        k3_scat2<<<(unsigned)((warps * 32 + 255) / 256), 256>>>(ei, E);
    }
    k4_mlpB <<<(N + 127) / 128, 128>>>(b1b, w2b, b2b, ws, N);
    k5_score<<<(C + 255) / 256, 256>>>(cand, bs, out, C);
}

// round 6
// speedup vs baseline: 2.5547x; 1.1223x over previous
#include <cuda_runtime.h>

#define MAXN 100000

// Static scratch (no allocation allowed)
__device__ float  d_x8[MAXN * 8];     // x padded to 8 (32B rows)
__device__ float  d_agg1[MAXN * 8];   // x + sum x[src], per dst
__device__ float  d_g[MAXN * 32];     // g = h_A @ w1b (128B rows)
__device__ float  d_agg2[MAXN * 32];  // sum g[src], per dst
__device__ float2 d_sc[MAXN];         // (s0, s1) per node

__device__ __forceinline__ void red_add_v4(float* p, float4 v) {
    asm volatile("red.global.add.v4.f32 [%0], {%1, %2, %3, %4};"
                 :: "l"(p), "f"(v.x), "f"(v.y), "f"(v.z), "f"(v.w) : "memory");
}

// kA: x8 <- [x,0], agg1 <- x8 (self term), agg2 <- 0
__global__ void kA_init(const float* __restrict__ x, int N) {
    int n = blockIdx.x * blockDim.x + threadIdx.x;
    if (n >= N) return;
    const float* xr = x + (size_t)n * 7;
    float4 lo = make_float4(__ldg(xr), __ldg(xr + 1), __ldg(xr + 2), __ldg(xr + 3));
    float4 hi = make_float4(__ldg(xr + 4), __ldg(xr + 5), __ldg(xr + 6), 0.f);
    ((float4*)(d_x8 + n * 8))[0] = lo;
    ((float4*)(d_x8 + n * 8))[1] = hi;
    ((float4*)(d_agg1 + n * 8))[0] = lo;
    ((float4*)(d_agg1 + n * 8))[1] = hi;
    float4 z = make_float4(0.f, 0.f, 0.f, 0.f);
    float4* a2 = (float4*)(d_agg2 + n * 32);
#pragma unroll
    for (int q = 0; q < 8; q++) a2[q] = z;
}

// k1: agg1[dst] += x8[src].  2 lanes x float4 per edge; 32 edges per warp (2 per lane-pair).
__global__ void __launch_bounds__(256) k1_scat1(const int* __restrict__ ei, int E) {
    int t = blockIdx.x * blockDim.x + threadIdx.x;
    int lane = t & 31;
    int p = lane >> 1;            // lane pair 0..15
    int q = lane & 1;             // float4 half
    long long base = (long long)(t >> 5) * 32;
#pragma unroll
    for (int r = 0; r < 2; r++) {
        long long e = base + r * 16 + p;
        if (e < E) {
            int s = __ldg(ei + e);
            int d = __ldg(ei + E + e);
            float4 v = __ldg((const float4*)(d_x8 + (size_t)s * 8) + q);
            red_add_v4(d_agg1 + (size_t)d * 8 + q * 4, v);
        }
    }
}

// k2: per node: t[7] -> relu(t@w1a+b1a) -> @w2a+b2a -> relu -> @w1b = g[32]
__global__ void __launch_bounds__(128) k2_mlpA(
    const float* __restrict__ w1a, const float* __restrict__ b1a,
    const float* __restrict__ w2a, const float* __restrict__ b2a,
    const float* __restrict__ w1b, int N) {
    __shared__ float s_w1a[7 * 64];
    __shared__ float s_b1a[64];
    __shared__ float s_w2a[64 * 64];
    __shared__ float s_b2a[64];
    __shared__ float s_w1b[64 * 32];
    for (int i = threadIdx.x; i < 112; i += 128)
        ((float4*)s_w1a)[i] = __ldg((const float4*)w1a + i);
    if (threadIdx.x < 64) { s_b1a[threadIdx.x] = b1a[threadIdx.x]; s_b2a[threadIdx.x] = b2a[threadIdx.x]; }
    for (int i = threadIdx.x; i < 1024; i += 128)
        ((float4*)s_w2a)[i] = __ldg((const float4*)w2a + i);
    for (int i = threadIdx.x; i < 512; i += 128)
        ((float4*)s_w1b)[i] = __ldg((const float4*)w1b + i);
    __syncthreads();

    int n = blockIdx.x * 128 + threadIdx.x;
    if (n >= N) return;

    float tin[7];
    const float* tr = d_agg1 + n * 8;
#pragma unroll
    for (int i = 0; i < 7; i++) tin[i] = tr[i];

    float acc[64];
#pragma unroll
    for (int j = 0; j < 64; j++) acc[j] = 0.f;
#pragma unroll 1
    for (int k = 0; k < 64; k++) {
        float h = s_b1a[k];
#pragma unroll
        for (int i = 0; i < 7; i++) h = fmaf(tin[i], s_w1a[i * 64 + k], h);
        h = fmaxf(h, 0.f);
#pragma unroll
        for (int j = 0; j < 64; j++) acc[j] = fmaf(h, s_w2a[k * 64 + j], acc[j]);
    }

    float g[32];
#pragma unroll
    for (int j = 0; j < 32; j++) g[j] = 0.f;
#pragma unroll 1
    for (int k = 0; k < 64; k++) {
        float h = fmaxf(acc[k] + s_b2a[k], 0.f);   // outer relu of layer A
#pragma unroll
        for (int j = 0; j < 32; j++) g[j] = fmaf(h, s_w1b[k * 32 + j], g[j]);
    }

    float4* gout = (float4*)(d_g + n * 32);
#pragma unroll
    for (int q = 0; q < 8; q++)
        gout[q] = make_float4(g[4 * q], g[4 * q + 1], g[4 * q + 2], g[4 * q + 3]);
}

// k3: agg2[dst] += g[src].  8 lanes x float4 per edge; 8 edges per warp (pair per group).
__global__ void __launch_bounds__(512) k3_scat2(const int* __restrict__ ei, int E) {
    int t = blockIdx.x * blockDim.x + threadIdx.x;
    int lane = t & 31;
    int grp = lane >> 3;          // 4 groups of 8 lanes
    int q = lane & 7;
    long long e0 = (long long)(t >> 5) * 8 + grp * 2;
    if (e0 >= E) return;
    int s0 = __ldg(ei + e0);
    int d0 = __ldg(ei + E + e0);
    bool has1 = (e0 + 1) < E;
    int s1 = 0, d1 = 0;
    if (has1) { s1 = __ldg(ei + e0 + 1); d1 = __ldg(ei + E + e0 + 1); }
    float4 v0 = __ldg((const float4*)(d_g + (size_t)s0 * 32) + q);
    float4 v1;
    if (has1) v1 = __ldg((const float4*)(d_g + (size_t)s1 * 32) + q);
    red_add_v4(d_agg2 + (size_t)d0 * 32 + q * 4, v0);
    if (has1) red_add_v4(d_agg2 + (size_t)d1 * 32 + q * 4, v1);
}

// k4: warp per node: a = relu(g + agg2 + b1b); h2 = a@w2b + b2b; s0/s1 via shfl reduce
__global__ void __launch_bounds__(256) k4_mlpB(
    const float* __restrict__ b1b, const float* __restrict__ w2b,
    const float* __restrict__ b2b, const float* __restrict__ ws, int N) {
    __shared__ float s_w2b[32 * 32];
    for (int i = threadIdx.x; i < 256; i += 256)
        ((float4*)s_w2b)[i] = __ldg((const float4*)w2b + i);
    __syncthreads();

    int lane = threadIdx.x & 31;
    int node = blockIdx.x * 8 + (threadIdx.x >> 5);
    if (node >= N) return;

    float acc = __ldg(d_g + (size_t)node * 32 + lane) + __ldg(d_agg2 + (size_t)node * 32 + lane);
    float a = fmaxf(acc + __ldg(b1b + lane), 0.f);

    float h2 = __ldg(b2b + lane);
#pragma unroll
    for (int k = 0; k < 32; k++) {
        float ak = __shfl_sync(0xffffffffu, a, k);
        h2 = fmaf(ak, s_w2b[k * 32 + lane], h2);
    }
    float s0 = h2 * __ldg(ws + lane);
    float s1 = h2 * __ldg(ws + 32 + lane);
#pragma unroll
    for (int o = 16; o > 0; o >>= 1) {
        s0 += __shfl_down_sync(0xffffffffu, s0, o);
        s1 += __shfl_down_sync(0xffffffffu, s1, o);
    }
    if (lane == 0) d_sc[node] = make_float2(s0, s1);
}

// k5: out[i] = sigmoid(s0[c0] + s1[c1] + bs).  2 candidates per thread via int4.
__global__ void k5_score(const int* __restrict__ cand, const float* __restrict__ bs,
                         float* __restrict__ out, int C) {
    int i = blockIdx.x * blockDim.x + threadIdx.x;
    int npair = C >> 1;
    float b = __ldg(bs);
    if (i < npair) {
        int4 c = __ldg((const int4*)cand + i);
        float z0 = d_sc[c.x].x + d_sc[c.y].y + b;
        float z1 = d_sc[c.z].x + d_sc[c.w].y + b;
        float2 o = make_float2(1.f / (1.f + __expf(-z0)), 1.f / (1.f + __expf(-z1)));
        ((float2*)out)[i] = o;
    }
    if ((C & 1) && i == 0) {
        int2 ce = __ldg((const int2*)cand + (C - 1));
        float z = d_sc[ce.x].x + d_sc[ce.y].y + b;
        out[C - 1] = 1.f / (1.f + __expf(-z));
    }
}

extern "C" void kernel_launch(void* const* d_in, const int* in_sizes, int n_in,
                              void* d_out, int out_size) {
    const float* x    = (const float*)d_in[0];
    const int*   ei   = (const int*)d_in[1];
    const int*   cand = (const int*)d_in[2];
    const float* w1a = (const float*)d_in[3];
    const float* b1a = (const float*)d_in[4];
    const float* w2a = (const float*)d_in[5];
    const float* b2a = (const float*)d_in[6];
    const float* w1b = (const float*)d_in[7];
    const float* b1b = (const float*)d_in[8];
    const float* w2b = (const float*)d_in[9];
    const float* b2b = (const float*)d_in[10];
    const float* ws  = (const float*)d_in[11];
    const float* bs  = (const float*)d_in[12];

    int N = in_sizes[0] / 7;
    int E = in_sizes[1] / 2;
    int C = in_sizes[2] / 2;
    float* out = (float*)d_out;

    kA_init <<<(N + 255) / 256, 256>>>(x, N);
    {   // k1: 32 edges per warp
        long long warps = ((long long)E + 31) / 32;
        k1_scat1<<<(unsigned)((warps * 32 + 255) / 256), 256>>>(ei, E);
    }
    k2_mlpA <<<(N + 127) / 128, 128>>>(w1a, b1a, w2a, b2a, w1b, N);
    {   // k3: 8 edges per warp
        long long warps = ((long long)E + 7) / 8;
        k3_scat2<<<(unsigned)((warps * 32 + 511) / 512), 512>>>(ei, E);
    }
    k4_mlpB <<<(N + 7) / 8, 256>>>(b1b, w2b, b2b, ws, N);
    k5_score<<<((C >> 1) + 255) / 256, 256>>>(cand, bs, out, C);
}

// round 7
// speedup vs baseline: 2.6847x; 1.0509x over previous
#include <cuda_runtime.h>

#define MAXN 100000
#define EMAX 6400000
#define SCAN_CHUNK 2048   // 512 threads x int4
#define MAXBLK 64

// Static scratch
__device__ float  d_x8[MAXN * 8];     // x padded to 8 (32B rows)
__device__ float  d_agg1[MAXN * 8];   // x + sum x[src]
__device__ float  d_g[MAXN * 32];     // g = h_A @ w1b (128B rows)
__device__ int    d_deg[MAXN];
__device__ int    d_off[MAXN + 4];    // exclusive prefix; d_off[N] = E
__device__ int    d_rank[EMAX];       // edge's rank within its dst bucket
__device__ int    d_srcs[EMAX];       // CSR: sources grouped by dst
__device__ int    d_bsum[MAXBLK];
__device__ int    d_boff[MAXBLK];
__device__ float2 d_sc[MAXN];

// kA: pad x into d_x8, zero deg
__global__ void kA_init(const float* __restrict__ x, int N) {
    int n = blockIdx.x * blockDim.x + threadIdx.x;
    if (n >= N) return;
    const float* xr = x + (size_t)n * 7;
    float4 lo = make_float4(__ldg(xr), __ldg(xr + 1), __ldg(xr + 2), __ldg(xr + 3));
    float4 hi = make_float4(__ldg(xr + 4), __ldg(xr + 5), __ldg(xr + 6), 0.f);
    ((float4*)(d_x8 + n * 8))[0] = lo;
    ((float4*)(d_x8 + n * 8))[1] = hi;
    d_deg[n] = 0;
}

// kH: histogram + per-edge rank (coalesced store)
__global__ void kH_hist(const int* __restrict__ ei, int E) {
    int e = blockIdx.x * blockDim.x + threadIdx.x;
    if (e >= E) return;
    int d = __ldg(ei + E + e);
    d_rank[e] = atomicAdd(&d_deg[d], 1);
}

// kS1: per-block sums of deg
__global__ void __launch_bounds__(512) kS1(int N) {
    __shared__ int s_w[16];
    int tid = threadIdx.x;
    int base = blockIdx.x * SCAN_CHUNK + tid * 4;
    int4 v = make_int4(0, 0, 0, 0);
    if (base < N) v = *(const int4*)(d_deg + base);
    int sum = v.x + v.y + v.z + v.w;
#pragma unroll
    for (int o = 16; o > 0; o >>= 1) sum += __shfl_down_sync(~0u, sum, o);
    if ((tid & 31) == 0) s_w[tid >> 5] = sum;
    __syncthreads();
    if (tid < 16) {
        int t = s_w[tid];
#pragma unroll
        for (int o = 8; o > 0; o >>= 1) t += __shfl_down_sync(0xffffu, t, o);
        if (tid == 0) d_bsum[blockIdx.x] = t;
    }
}

// kS2: serial scan of block sums (NB <= 64), write total to d_off[N]
__global__ void kS2(int NB, int N) {
    int run = 0;
    for (int b = 0; b < NB; b++) { d_boff[b] = run; run += d_bsum[b]; }
    d_off[N] = run;
}

// kS3: block-level exclusive scan + global offset -> d_off
__global__ void __launch_bounds__(512) kS3(int N) {
    __shared__ int s_w[16];
    int tid = threadIdx.x;
    int lane = tid & 31, wid = tid >> 5;
    int base = blockIdx.x * SCAN_CHUNK + tid * 4;
    int4 v = make_int4(0, 0, 0, 0);
    if (base < N) v = *(const int4*)(d_deg + base);
    int t1 = v.x + v.y, t2 = t1 + v.z, tot = t2 + v.w;
    int scan = tot;
#pragma unroll
    for (int o = 1; o < 32; o <<= 1) {
        int nv = __shfl_up_sync(~0u, scan, o);
        if (lane >= o) scan += nv;
    }
    if (lane == 31) s_w[wid] = scan;
    __syncthreads();
    if (wid == 0 && lane < 16) {
        int w = s_w[lane];
#pragma unroll
        for (int o = 1; o < 16; o <<= 1) {
            int nv = __shfl_up_sync(0xffffu, w, o);
            if (lane >= o) w += nv;
        }
        s_w[lane] = w;
    }
    __syncthreads();
    int excl = scan - tot + (wid > 0 ? s_w[wid - 1] : 0) + d_boff[blockIdx.x];
    if (base < N)
        *(int4*)(d_off + base) = make_int4(excl, excl + v.x, excl + t1, excl + t2);
}

// kP: place srcs into CSR (no atomics)
__global__ void kP_place(const int* __restrict__ ei, int E) {
    int e = blockIdx.x * blockDim.x + threadIdx.x;
    if (e >= E) return;
    int s = __ldg(ei + e);
    int d = __ldg(ei + E + e);
    d_srcs[__ldg(d_off + d) + d_rank[e]] = s;
}

// kE: agg1[n] = x8[n] + sum x8[src].  8 lanes/node, 4 nodes/warp.
__global__ void __launch_bounds__(256) kE_agg1(int N) {
    int tid = blockIdx.x * blockDim.x + threadIdx.x;
    int node = tid >> 3;
    int j = tid & 7;
    if (node >= N) return;
    int beg = __ldg(d_off + node), end = __ldg(d_off + node + 1);
    float acc = d_x8[(size_t)node * 8 + j];
    int i = beg;
    for (; i + 1 < end; i += 2) {
        int s0 = __ldg(d_srcs + i);
        int s1 = __ldg(d_srcs + i + 1);
        acc += __ldg(d_x8 + (size_t)s0 * 8 + j);
        acc += __ldg(d_x8 + (size_t)s1 * 8 + j);
    }
    if (i < end) {
        int s = __ldg(d_srcs + i);
        acc += __ldg(d_x8 + (size_t)s * 8 + j);
    }
    d_agg1[(size_t)node * 8 + j] = acc;
}

// k2: per node: t[7] -> relu(t@w1a+b1a) -> @w2a+b2a -> relu -> @w1b = g[32]
__global__ void __launch_bounds__(128) k2_mlpA(
    const float* __restrict__ w1a, const float* __restrict__ b1a,
    const float* __restrict__ w2a, const float* __restrict__ b2a,
    const float* __restrict__ w1b, int N) {
    __shared__ float s_w1a[7 * 64];
    __shared__ float s_b1a[64];
    __shared__ float s_w2a[64 * 64];
    __shared__ float s_b2a[64];
    __shared__ float s_w1b[64 * 32];
    for (int i = threadIdx.x; i < 112; i += 128)
        ((float4*)s_w1a)[i] = __ldg((const float4*)w1a + i);
    if (threadIdx.x < 64) { s_b1a[threadIdx.x] = b1a[threadIdx.x]; s_b2a[threadIdx.x] = b2a[threadIdx.x]; }
    for (int i = threadIdx.x; i < 1024; i += 128)
        ((float4*)s_w2a)[i] = __ldg((const float4*)w2a + i);
    for (int i = threadIdx.x; i < 512; i += 128)
        ((float4*)s_w1b)[i] = __ldg((const float4*)w1b + i);
    __syncthreads();

    int n = blockIdx.x * 128 + threadIdx.x;
    if (n >= N) return;

    float tin[7];
    const float* tr = d_agg1 + (size_t)n * 8;
#pragma unroll
    for (int i = 0; i < 7; i++) tin[i] = tr[i];

    float acc[64];
#pragma unroll
    for (int j = 0; j < 64; j++) acc[j] = 0.f;
#pragma unroll 1
    for (int k = 0; k < 64; k++) {
        float h = s_b1a[k];
#pragma unroll
        for (int i = 0; i < 7; i++) h = fmaf(tin[i], s_w1a[i * 64 + k], h);
        h = fmaxf(h, 0.f);
#pragma unroll
        for (int j = 0; j < 64; j++) acc[j] = fmaf(h, s_w2a[k * 64 + j], acc[j]);
    }

    float g[32];
#pragma unroll
    for (int j = 0; j < 32; j++) g[j] = 0.f;
#pragma unroll 1
    for (int k = 0; k < 64; k++) {
        float h = fmaxf(acc[k] + s_b2a[k], 0.f);
#pragma unroll
        for (int j = 0; j < 32; j++) g[j] = fmaf(h, s_w1b[k * 32 + j], g[j]);
    }

    float4* gout = (float4*)(d_g + (size_t)n * 32);
#pragma unroll
    for (int q = 0; q < 8; q++)
        gout[q] = make_float4(g[4 * q], g[4 * q + 1], g[4 * q + 2], g[4 * q + 3]);
}

// kF: warp/node: agg2 = g[n] + sum g[src] (4 groups x 8 lanes x float4), fused mlpB + score
__global__ void __launch_bounds__(256) kF_agg2_mlpB(
    const float* __restrict__ b1b, const float* __restrict__ w2b,
    const float* __restrict__ b2b, const float* __restrict__ ws, int N) {
    __shared__ float s_w2b[32 * 32];
    for (int i = threadIdx.x; i < 256; i += 256)
        ((float4*)s_w2b)[i] = __ldg((const float4*)w2b + i);
    __syncthreads();

    int lane = threadIdx.x & 31;
    int grp = lane >> 3;
    int j = lane & 7;
    int node = blockIdx.x * 8 + (threadIdx.x >> 5);
    if (node >= N) return;

    int beg = __ldg(d_off + node), end = __ldg(d_off + node + 1);
    float4 acc = make_float4(0.f, 0.f, 0.f, 0.f);
    if (grp == 0) acc = __ldg((const float4*)(d_g + (size_t)node * 32) + j);
#pragma unroll 2
    for (int i = beg + grp; i < end; i += 4) {
        int s = __ldg(d_srcs + i);
        float4 v = __ldg((const float4*)(d_g + (size_t)s * 32) + j);
        acc.x += v.x; acc.y += v.y; acc.z += v.z; acc.w += v.w;
    }
    // reduce across 4 groups (lanes l, l^8, l^16, l^24 hold same dims)
#pragma unroll
    for (int o = 8; o <= 16; o <<= 1) {
        acc.x += __shfl_xor_sync(~0u, acc.x, o);
        acc.y += __shfl_xor_sync(~0u, acc.y, o);
        acc.z += __shfl_xor_sync(~0u, acc.z, o);
        acc.w += __shfl_xor_sync(~0u, acc.w, o);
    }
    float4 bb = __ldg((const float4*)b1b + j);
    float4 a4;
    a4.x = fmaxf(acc.x + bb.x, 0.f);
    a4.y = fmaxf(acc.y + bb.y, 0.f);
    a4.z = fmaxf(acc.z + bb.z, 0.f);
    a4.w = fmaxf(acc.w + bb.w, 0.f);

    // h2[lane] = b2b[lane] + sum_k a[k] * w2b[k*32+lane]
    float h2 = __ldg(b2b + lane);
#pragma unroll
    for (int jj = 0; jj < 8; jj++) {
        float a0 = __shfl_sync(~0u, a4.x, jj);
        float a1 = __shfl_sync(~0u, a4.y, jj);
        float a2 = __shfl_sync(~0u, a4.z, jj);
        float a3 = __shfl_sync(~0u, a4.w, jj);
        h2 = fmaf(a0, s_w2b[(4 * jj + 0) * 32 + lane], h2);
        h2 = fmaf(a1, s_w2b[(4 * jj + 1) * 32 + lane], h2);
        h2 = fmaf(a2, s_w2b[(4 * jj + 2) * 32 + lane], h2);
        h2 = fmaf(a3, s_w2b[(4 * jj + 3) * 32 + lane], h2);
    }
    float s0 = h2 * __ldg(ws + lane);
    float s1 = h2 * __ldg(ws + 32 + lane);
#pragma unroll
    for (int o = 16; o > 0; o >>= 1) {
        s0 += __shfl_down_sync(~0u, s0, o);
        s1 += __shfl_down_sync(~0u, s1, o);
    }
    if (lane == 0) d_sc[node] = make_float2(s0, s1);
}

// k5: out[i] = sigmoid(s0[c0] + s1[c1] + bs).  2 candidates per thread.
__global__ void k5_score(const int* __restrict__ cand, const float* __restrict__ bs,
                         float* __restrict__ out, int C) {
    int i = blockIdx.x * blockDim.x + threadIdx.x;
    int npair = C >> 1;
    float b = __ldg(bs);
    if (i < npair) {
        int4 c = __ldg((const int4*)cand + i);
        float z0 = d_sc[c.x].x + d_sc[c.y].y + b;
        float z1 = d_sc[c.z].x + d_sc[c.w].y + b;
        ((float2*)out)[i] = make_float2(1.f / (1.f + __expf(-z0)),
                                        1.f / (1.f + __expf(-z1)));
    }
    if ((C & 1) && i == 0) {
        int2 ce = __ldg((const int2*)cand + (C - 1));
        float z = d_sc[ce.x].x + d_sc[ce.y].y + b;
        out[C - 1] = 1.f / (1.f + __expf(-z));
    }
}

extern "C" void kernel_launch(void* const* d_in, const int* in_sizes, int n_in,
                              void* d_out, int out_size) {
    const float* x    = (const float*)d_in[0];
    const int*   ei   = (const int*)d_in[1];
    const int*   cand = (const int*)d_in[2];
    const float* w1a = (const float*)d_in[3];
    const float* b1a = (const float*)d_in[4];
    const float* w2a = (const float*)d_in[5];
    const float* b2a = (const float*)d_in[6];
    const float* w1b = (const float*)d_in[7];
    const float* b1b = (const float*)d_in[8];
    const float* w2b = (const float*)d_in[9];
    const float* b2b = (const float*)d_in[10];
    const float* ws  = (const float*)d_in[11];
    const float* bs  = (const float*)d_in[12];

    int N = in_sizes[0] / 7;
    int E = in_sizes[1] / 2;
    int C = in_sizes[2] / 2;
    float* out = (float*)d_out;
    int NB = (N + SCAN_CHUNK - 1) / SCAN_CHUNK;

    kA_init <<<(N + 255) / 256, 256>>>(x, N);
    kH_hist <<<(E + 255) / 256, 256>>>(ei, E);
    kS1     <<<NB, 512>>>(N);
    kS2     <<<1, 1>>>(NB, N);
    kS3     <<<NB, 512>>>(N);
    kP_place<<<(E + 255) / 256, 256>>>(ei, E);
    kE_agg1 <<<(N * 8 + 255) / 256, 256>>>(N);
    k2_mlpA <<<(N + 127) / 128, 128>>>(w1a, b1a, w2a, b2a, w1b, N);
    kF_agg2_mlpB<<<(N + 7) / 8, 256>>>(b1b, w2b, b2b, ws, N);
    k5_score<<<((C >> 1) + 255) / 256, 256>>>(cand, bs, out, C);
}